// round 2
// baseline (speedup 1.0000x reference)
#include <cuda_runtime.h>
#include <cuda_bf16.h>
#include <cstdint>

#define NB 1024
#define NT 256
#define NC 512
#define NH 64

// ---------------- scratch (static device globals; no allocation) ----------------
__device__ __nv_bfloat16 g_qh[NB*NT*NH];
__device__ __nv_bfloat16 g_ql[NB*NT*NH];
__device__ __nv_bfloat16 g_kh[NB*NT*NH];
__device__ __nv_bfloat16 g_kl[NB*NT*NH];
__device__ __nv_bfloat16 g_vh[NB*NT*NH];
__device__ __nv_bfloat16 g_vl[NB*NT*NH];
__device__ __nv_bfloat16 g_wth[192*512];   // [n192][k] transposed hi
__device__ __nv_bfloat16 g_wtl[192*512];   // [n192][k] transposed lo

// ---------------- helpers ----------------
__device__ __forceinline__ void mma16816(float* d, const uint32_t* a, const uint32_t* b){
  asm volatile(
    "mma.sync.aligned.m16n8k16.row.col.f32.bf16.bf16.f32 "
    "{%0,%1,%2,%3},{%4,%5,%6,%7},{%8,%9},{%0,%1,%2,%3};\n"
    : "+f"(d[0]), "+f"(d[1]), "+f"(d[2]), "+f"(d[3])
    : "r"(a[0]), "r"(a[1]), "r"(a[2]), "r"(a[3]), "r"(b[0]), "r"(b[1]));
}

__device__ __forceinline__ uint32_t pack_hi2(float a, float b){
  __nv_bfloat162 t = __floats2bfloat162_rn(a, b);   // .x = a (low), .y = b (high)
  return *reinterpret_cast<uint32_t*>(&t);
}
__device__ __forceinline__ uint32_t pack_lo2(float a, float b){
  float ah = __bfloat162float(__float2bfloat16(a));
  float bh = __bfloat162float(__float2bfloat16(b));
  __nv_bfloat162 t = __floats2bfloat162_rn(a - ah, b - bh);
  return *reinterpret_cast<uint32_t*>(&t);
}

// ---------------- kernel 0: split + transpose weights ----------------
__global__ void prep_w_kernel(const float* __restrict__ Wq,
                              const float* __restrict__ Wk,
                              const float* __restrict__ Wv){
  int idx = blockIdx.x*blockDim.x + threadIdx.x;
  if (idx >= 192*512) return;
  int n192 = idx >> 9, k = idx & 511;
  int mat = n192 >> 6, n = n192 & 63;
  const float* W = (mat == 0) ? Wq : (mat == 1 ? Wk : Wv);
  float v = W[k*NH + n];
  __nv_bfloat16 h = __float2bfloat16(v);
  g_wth[idx] = h;
  g_wtl[idx] = __float2bfloat16(v - __bfloat162float(h));
}

// ---------------- kernel 1: fused QKV projection (split-bf16 MMA) ----------------
// CTA: 128 rows x 192 cols (Q|K|V), K-chunks of 64. 8 warps = 4(m) x 2(n), warp tile 32x96.
#define K1_XS 9216            // 128*72 halves
#define K1_WS 13824           // 192*72 halves
#define K1_SMEM ((2*K1_XS + 2*K1_WS)*2)

__global__ __launch_bounds__(256, 1) void qkv_kernel(const float* __restrict__ x){
  extern __shared__ __nv_bfloat16 sm1[];
  __nv_bfloat16* xh = sm1;
  __nv_bfloat16* xl = sm1 + K1_XS;
  __nv_bfloat16* wh = sm1 + 2*K1_XS;
  __nv_bfloat16* wl = wh  + K1_WS;

  const int t = threadIdx.x;
  const int w = t >> 5, lane = t & 31, g = lane >> 2, t4 = lane & 3;
  const int mw = w & 3, nw = w >> 2;
  const int row0 = blockIdx.x * 128;

  float acc[2][12][4];
  #pragma unroll
  for (int mt = 0; mt < 2; mt++)
    #pragma unroll
    for (int nt = 0; nt < 12; nt++)
      #pragma unroll
      for (int e = 0; e < 4; e++) acc[mt][nt][e] = 0.f;

  for (int kc = 0; kc < 8; kc++){
    // stage x tile (128 x 64 fp32 -> hi/lo bf16, padded stride 72)
    #pragma unroll
    for (int i = 0; i < 8; i++){
      int idx4 = i*256 + t;
      int r = idx4 >> 4, c4 = (idx4 & 15) << 2;
      float4 v = *reinterpret_cast<const float4*>(x + (size_t)(row0 + r)*NC + kc*64 + c4);
      __nv_bfloat162 h01, h23, l01, l23;
      h01.x = __float2bfloat16(v.x); l01.x = __float2bfloat16(v.x - __bfloat162float(h01.x));
      h01.y = __float2bfloat16(v.y); l01.y = __float2bfloat16(v.y - __bfloat162float(h01.y));
      h23.x = __float2bfloat16(v.z); l23.x = __float2bfloat16(v.z - __bfloat162float(h23.x));
      h23.y = __float2bfloat16(v.w); l23.y = __float2bfloat16(v.w - __bfloat162float(h23.y));
      *reinterpret_cast<__nv_bfloat162*>(&xh[r*72 + c4    ]) = h01;
      *reinterpret_cast<__nv_bfloat162*>(&xh[r*72 + c4 + 2]) = h23;
      *reinterpret_cast<__nv_bfloat162*>(&xl[r*72 + c4    ]) = l01;
      *reinterpret_cast<__nv_bfloat162*>(&xl[r*72 + c4 + 2]) = l23;
    }
    // stage W tiles (already split/transposed bf16, k-contiguous)
    #pragma unroll
    for (int i = 0; i < 12; i++){
      int idx4 = i*256 + t;
      int n192 = idx4 >> 4, c4 = (idx4 & 15) << 2;
      *reinterpret_cast<uint2*>(&wh[n192*72 + c4]) =
          *reinterpret_cast<const uint2*>(&g_wth[n192*512 + kc*64 + c4]);
      *reinterpret_cast<uint2*>(&wl[n192*72 + c4]) =
          *reinterpret_cast<const uint2*>(&g_wtl[n192*512 + kc*64 + c4]);
    }
    __syncthreads();

    #pragma unroll
    for (int ks = 0; ks < 4; ks++){
      int ko = ks*16;
      uint32_t ah[2][4], al[2][4];
      #pragma unroll
      for (int mt = 0; mt < 2; mt++){
        int rb = mw*32 + mt*16;
        ah[mt][0] = *reinterpret_cast<const uint32_t*>(&xh[(rb+g  )*72 + ko + 2*t4    ]);
        ah[mt][1] = *reinterpret_cast<const uint32_t*>(&xh[(rb+g+8)*72 + ko + 2*t4    ]);
        ah[mt][2] = *reinterpret_cast<const uint32_t*>(&xh[(rb+g  )*72 + ko + 2*t4 + 8]);
        ah[mt][3] = *reinterpret_cast<const uint32_t*>(&xh[(rb+g+8)*72 + ko + 2*t4 + 8]);
        al[mt][0] = *reinterpret_cast<const uint32_t*>(&xl[(rb+g  )*72 + ko + 2*t4    ]);
        al[mt][1] = *reinterpret_cast<const uint32_t*>(&xl[(rb+g+8)*72 + ko + 2*t4    ]);
        al[mt][2] = *reinterpret_cast<const uint32_t*>(&xl[(rb+g  )*72 + ko + 2*t4 + 8]);
        al[mt][3] = *reinterpret_cast<const uint32_t*>(&xl[(rb+g+8)*72 + ko + 2*t4 + 8]);
      }
      #pragma unroll
      for (int nt = 0; nt < 12; nt++){
        int nb = nw*96 + nt*8;
        uint32_t bh[2], bl[2];
        bh[0] = *reinterpret_cast<const uint32_t*>(&wh[(nb+g)*72 + ko + 2*t4    ]);
        bh[1] = *reinterpret_cast<const uint32_t*>(&wh[(nb+g)*72 + ko + 2*t4 + 8]);
        bl[0] = *reinterpret_cast<const uint32_t*>(&wl[(nb+g)*72 + ko + 2*t4    ]);
        bl[1] = *reinterpret_cast<const uint32_t*>(&wl[(nb+g)*72 + ko + 2*t4 + 8]);
        #pragma unroll
        for (int mt = 0; mt < 2; mt++){
          mma16816(acc[mt][nt], ah[mt], bh);
          mma16816(acc[mt][nt], ah[mt], bl);
          mma16816(acc[mt][nt], al[mt], bh);
        }
      }
    }
    __syncthreads();
  }

  // epilogue: split fp32 accum -> hi/lo bf16 scratch
  #pragma unroll
  for (int mt = 0; mt < 2; mt++){
    #pragma unroll
    for (int nt = 0; nt < 12; nt++){
      int col = nw*96 + nt*8 + 2*t4;
      int mat = col >> 6, h = col & 63;
      __nv_bfloat16* dh = (mat == 0) ? g_qh : (mat == 1 ? g_kh : g_vh);
      __nv_bfloat16* dl = (mat == 0) ? g_ql : (mat == 1 ? g_kl : g_vl);
      int r0g = row0 + mw*32 + mt*16 + g;
      float c0 = acc[mt][nt][0], c1 = acc[mt][nt][1];
      float c2 = acc[mt][nt][2], c3 = acc[mt][nt][3];
      __nv_bfloat162 hh, ll;
      hh.x = __float2bfloat16(c0); ll.x = __float2bfloat16(c0 - __bfloat162float(hh.x));
      hh.y = __float2bfloat16(c1); ll.y = __float2bfloat16(c1 - __bfloat162float(hh.y));
      *reinterpret_cast<__nv_bfloat162*>(&dh[(size_t)r0g*NH + h]) = hh;
      *reinterpret_cast<__nv_bfloat162*>(&dl[(size_t)r0g*NH + h]) = ll;
      hh.x = __float2bfloat16(c2); ll.x = __float2bfloat16(c2 - __bfloat162float(hh.x));
      hh.y = __float2bfloat16(c3); ll.y = __float2bfloat16(c3 - __bfloat162float(hh.y));
      *reinterpret_cast<__nv_bfloat162*>(&dh[(size_t)(r0g+8)*NH + h]) = hh;
      *reinterpret_cast<__nv_bfloat162*>(&dl[(size_t)(r0g+8)*NH + h]) = ll;
    }
  }
}

// ---------------- kernel 2: causal attention (flash-style, split-bf16 MMA) ----------------
// CTA = (batch, 128-row block). 8 warps x 16 query rows. Keys/values staged in smem.
#define A_QH 0
#define A_QL 9216
#define A_KH 18432
#define A_KL 36864
#define A_VH 55296
#define A_VL 72320
#define A_TOT 89344
#define K2_SMEM (A_TOT*2)
#define VSTR 266

__global__ __launch_bounds__(256, 1) void attn_kernel(float* __restrict__ out){
  extern __shared__ __nv_bfloat16 sm2[];
  __nv_bfloat16* qh  = sm2 + A_QH;
  __nv_bfloat16* ql  = sm2 + A_QL;
  __nv_bfloat16* kh  = sm2 + A_KH;
  __nv_bfloat16* kl  = sm2 + A_KL;
  __nv_bfloat16* vth = sm2 + A_VH;
  __nv_bfloat16* vtl = sm2 + A_VL;

  const int b   = blockIdx.x >> 1;
  const int blk = blockIdx.x & 1;
  const int t = threadIdx.x, w = t >> 5, lane = t & 31, g = lane >> 2, t4 = lane & 3;
  const int nk = (blk + 1) * 128;                 // causal: only this many keys needed
  const size_t base = (size_t)b * (NT*NH);

  // Q (this block's 128 rows)
  #pragma unroll
  for (int i = 0; i < 8; i++){
    int idx4 = i*256 + t;
    int r = idx4 >> 4, c4 = (idx4 & 15) << 2;
    *reinterpret_cast<uint2*>(&qh[r*72 + c4]) =
        *reinterpret_cast<const uint2*>(&g_qh[base + (size_t)(blk*128 + r)*NH + c4]);
    *reinterpret_cast<uint2*>(&ql[r*72 + c4]) =
        *reinterpret_cast<const uint2*>(&g_ql[base + (size_t)(blk*128 + r)*NH + c4]);
  }
  // K (rows 0..nk)
  for (int idx4 = t; idx4 < nk*16; idx4 += 256){
    int r = idx4 >> 4, c4 = (idx4 & 15) << 2;
    *reinterpret_cast<uint2*>(&kh[r*72 + c4]) =
        *reinterpret_cast<const uint2*>(&g_kh[base + (size_t)r*NH + c4]);
    *reinterpret_cast<uint2*>(&kl[r*72 + c4]) =
        *reinterpret_cast<const uint2*>(&g_kl[base + (size_t)r*NH + c4]);
  }
  // V transposed: vt[h][s]
  for (int idx4 = t; idx4 < nk*16; idx4 += 256){
    int s = idx4 >> 4, h4 = (idx4 & 15) << 2;
    uint2 vh2 = *reinterpret_cast<const uint2*>(&g_vh[base + (size_t)s*NH + h4]);
    uint2 vl2 = *reinterpret_cast<const uint2*>(&g_vl[base + (size_t)s*NH + h4]);
    const __nv_bfloat162* ph = reinterpret_cast<const __nv_bfloat162*>(&vh2);
    const __nv_bfloat162* pl = reinterpret_cast<const __nv_bfloat162*>(&vl2);
    vth[(h4+0)*VSTR + s] = ph[0].x;  vth[(h4+1)*VSTR + s] = ph[0].y;
    vth[(h4+2)*VSTR + s] = ph[1].x;  vth[(h4+3)*VSTR + s] = ph[1].y;
    vtl[(h4+0)*VSTR + s] = pl[0].x;  vtl[(h4+1)*VSTR + s] = pl[0].y;
    vtl[(h4+2)*VSTR + s] = pl[1].x;  vtl[(h4+3)*VSTR + s] = pl[1].y;
  }
  __syncthreads();

  const int rb  = blk*128 + w*16;    // global query-row base for this warp
  const int lrb = w*16;              // local row base in qh/ql
  float m_[2] = {-1e30f, -1e30f};
  float l_[2] = {0.f, 0.f};
  float o[8][4];
  #pragma unroll
  for (int nt = 0; nt < 8; nt++)
    #pragma unroll
    for (int e = 0; e < 4; e++) o[nt][e] = 0.f;

  const int jmax = (rb + 15) >> 6;
  for (int j = 0; j <= jmax; j++){
    // ---- S = Q K^T (64-wide key chunk) ----
    float s[8][4];
    #pragma unroll
    for (int nt = 0; nt < 8; nt++)
      #pragma unroll
      for (int e = 0; e < 4; e++) s[nt][e] = 0.f;

    #pragma unroll
    for (int ks = 0; ks < 4; ks++){
      int ko = ks*16;
      uint32_t ah[4], al[4];
      ah[0] = *reinterpret_cast<const uint32_t*>(&qh[(lrb+g  )*72 + ko + 2*t4    ]);
      ah[1] = *reinterpret_cast<const uint32_t*>(&qh[(lrb+g+8)*72 + ko + 2*t4    ]);
      ah[2] = *reinterpret_cast<const uint32_t*>(&qh[(lrb+g  )*72 + ko + 2*t4 + 8]);
      ah[3] = *reinterpret_cast<const uint32_t*>(&qh[(lrb+g+8)*72 + ko + 2*t4 + 8]);
      al[0] = *reinterpret_cast<const uint32_t*>(&ql[(lrb+g  )*72 + ko + 2*t4    ]);
      al[1] = *reinterpret_cast<const uint32_t*>(&ql[(lrb+g+8)*72 + ko + 2*t4    ]);
      al[2] = *reinterpret_cast<const uint32_t*>(&ql[(lrb+g  )*72 + ko + 2*t4 + 8]);
      al[3] = *reinterpret_cast<const uint32_t*>(&ql[(lrb+g+8)*72 + ko + 2*t4 + 8]);
      #pragma unroll
      for (int nt = 0; nt < 8; nt++){
        int kr = j*64 + nt*8 + g;
        uint32_t bh[2], bl[2];
        bh[0] = *reinterpret_cast<const uint32_t*>(&kh[kr*72 + ko + 2*t4    ]);
        bh[1] = *reinterpret_cast<const uint32_t*>(&kh[kr*72 + ko + 2*t4 + 8]);
        bl[0] = *reinterpret_cast<const uint32_t*>(&kl[kr*72 + ko + 2*t4    ]);
        bl[1] = *reinterpret_cast<const uint32_t*>(&kl[kr*72 + ko + 2*t4 + 8]);
        mma16816(s[nt], ah, bh);
        mma16816(s[nt], ah, bl);
        mma16816(s[nt], al, bh);
      }
    }

    // ---- scale + causal mask ----
    const bool needm = (j*64 + 63 > rb);
    #pragma unroll
    for (int nt = 0; nt < 8; nt++){
      #pragma unroll
      for (int e = 0; e < 4; e++){
        float v = s[nt][e] * 0.125f;
        if (needm){
          int col = j*64 + nt*8 + 2*t4 + (e & 1);
          int row = rb + g + ((e & 2) ? 8 : 0);
          if (col > row) v = -1e30f;
        }
        s[nt][e] = v;
      }
    }

    // ---- online softmax update ----
    float mx0 = -1e30f, mx1 = -1e30f;
    #pragma unroll
    for (int nt = 0; nt < 8; nt++){
      mx0 = fmaxf(mx0, fmaxf(s[nt][0], s[nt][1]));
      mx1 = fmaxf(mx1, fmaxf(s[nt][2], s[nt][3]));
    }
    mx0 = fmaxf(mx0, __shfl_xor_sync(0xffffffffu, mx0, 1));
    mx0 = fmaxf(mx0, __shfl_xor_sync(0xffffffffu, mx0, 2));
    mx1 = fmaxf(mx1, __shfl_xor_sync(0xffffffffu, mx1, 1));
    mx1 = fmaxf(mx1, __shfl_xor_sync(0xffffffffu, mx1, 2));
    float mn0 = fmaxf(m_[0], mx0), mn1 = fmaxf(m_[1], mx1);
    float cr0 = __expf(m_[0] - mn0), cr1 = __expf(m_[1] - mn1);
    m_[0] = mn0; m_[1] = mn1;

    float rs0 = 0.f, rs1 = 0.f;
    #pragma unroll
    for (int nt = 0; nt < 8; nt++){
      s[nt][0] = __expf(s[nt][0] - mn0); rs0 += s[nt][0];
      s[nt][1] = __expf(s[nt][1] - mn0); rs0 += s[nt][1];
      s[nt][2] = __expf(s[nt][2] - mn1); rs1 += s[nt][2];
      s[nt][3] = __expf(s[nt][3] - mn1); rs1 += s[nt][3];
    }
    rs0 += __shfl_xor_sync(0xffffffffu, rs0, 1);
    rs0 += __shfl_xor_sync(0xffffffffu, rs0, 2);
    rs1 += __shfl_xor_sync(0xffffffffu, rs1, 1);
    rs1 += __shfl_xor_sync(0xffffffffu, rs1, 2);
    l_[0] = l_[0]*cr0 + rs0;
    l_[1] = l_[1]*cr1 + rs1;
    #pragma unroll
    for (int nt = 0; nt < 8; nt++){
      o[nt][0] *= cr0; o[nt][1] *= cr0;
      o[nt][2] *= cr1; o[nt][3] *= cr1;
    }

    // ---- O += P V (register-reuse A-fragments, hi/lo split) ----
    #pragma unroll
    for (int ks2 = 0; ks2 < 4; ks2++){
      uint32_t ph[4], pl[4];
      ph[0] = pack_hi2(s[2*ks2  ][0], s[2*ks2  ][1]);
      ph[1] = pack_hi2(s[2*ks2  ][2], s[2*ks2  ][3]);
      ph[2] = pack_hi2(s[2*ks2+1][0], s[2*ks2+1][1]);
      ph[3] = pack_hi2(s[2*ks2+1][2], s[2*ks2+1][3]);
      pl[0] = pack_lo2(s[2*ks2  ][0], s[2*ks2  ][1]);
      pl[1] = pack_lo2(s[2*ks2  ][2], s[2*ks2  ][3]);
      pl[2] = pack_lo2(s[2*ks2+1][0], s[2*ks2+1][1]);
      pl[3] = pack_lo2(s[2*ks2+1][2], s[2*ks2+1][3]);
      int sb = j*64 + ks2*16;
      #pragma unroll
      for (int nt2 = 0; nt2 < 8; nt2++){
        uint32_t bh[2], bl[2];
        bh[0] = *reinterpret_cast<const uint32_t*>(&vth[(nt2*8+g)*VSTR + sb + 2*t4    ]);
        bh[1] = *reinterpret_cast<const uint32_t*>(&vth[(nt2*8+g)*VSTR + sb + 2*t4 + 8]);
        bl[0] = *reinterpret_cast<const uint32_t*>(&vtl[(nt2*8+g)*VSTR + sb + 2*t4    ]);
        bl[1] = *reinterpret_cast<const uint32_t*>(&vtl[(nt2*8+g)*VSTR + sb + 2*t4 + 8]);
        mma16816(o[nt2], ph, bh);
        mma16816(o[nt2], ph, bl);
        mma16816(o[nt2], pl, bh);
      }
    }
  }

  // ---- epilogue ----
  float inv0 = 1.f / l_[0], inv1 = 1.f / l_[1];
  #pragma unroll
  for (int nt2 = 0; nt2 < 8; nt2++){
    int col = nt2*8 + 2*t4;
    size_t o0 = base + (size_t)(rb + g)*NH + col;
    float2 v01 = make_float2(o[nt2][0]*inv0, o[nt2][1]*inv0);
    float2 v23 = make_float2(o[nt2][2]*inv1, o[nt2][3]*inv1);
    *reinterpret_cast<float2*>(&out[o0])          = v01;
    *reinterpret_cast<float2*>(&out[o0 + 8*NH])   = v23;
  }
}

// ---------------- launch ----------------
extern "C" void kernel_launch(void* const* d_in, const int* in_sizes, int n_in,
                              void* d_out, int out_size){
  const float* x  = (const float*)d_in[0];
  const float* Wq = (const float*)d_in[1];
  const float* Wk = (const float*)d_in[2];
  const float* Wv = (const float*)d_in[3];
  float* out = (float*)d_out;

  cudaFuncSetAttribute(qkv_kernel,  cudaFuncAttributeMaxDynamicSharedMemorySize, K1_SMEM);
  cudaFuncSetAttribute(attn_kernel, cudaFuncAttributeMaxDynamicSharedMemorySize, K2_SMEM);

  prep_w_kernel<<<384, 256>>>(Wq, Wk, Wv);
  qkv_kernel<<<2048, 256, K1_SMEM>>>(x);
  attn_kernel<<<2048, 256, K2_SMEM>>>(out);
}

// round 5
// speedup vs baseline: 1.0841x; 1.0841x over previous
#include <cuda_runtime.h>
#include <cuda_bf16.h>
#include <cstdint>

#define NB 1024
#define NT 256
#define NC 512
#define NH 64

// ---------------- scratch (static device globals; no allocation) ----------------
__device__ __nv_bfloat16 g_qh[NB*NT*NH];
__device__ __nv_bfloat16 g_ql[NB*NT*NH];
__device__ __nv_bfloat16 g_kh[NB*NT*NH];
__device__ __nv_bfloat16 g_kl[NB*NT*NH];
__device__ __nv_bfloat16 g_vh[NB*NT*NH];
__device__ __nv_bfloat16 g_vl[NB*NT*NH];
__device__ __nv_bfloat16 g_wth[192*512];   // [n192][k] transposed hi
__device__ __nv_bfloat16 g_wtl[192*512];   // [n192][k] transposed lo

// ---------------- helpers ----------------
__device__ __forceinline__ void mma16816(float* d, const uint32_t* a, const uint32_t* b){
  asm volatile(
    "mma.sync.aligned.m16n8k16.row.col.f32.bf16.bf16.f32 "
    "{%0,%1,%2,%3},{%4,%5,%6,%7},{%8,%9},{%0,%1,%2,%3};\n"
    : "+f"(d[0]), "+f"(d[1]), "+f"(d[2]), "+f"(d[3])
    : "r"(a[0]), "r"(a[1]), "r"(a[2]), "r"(a[3]), "r"(b[0]), "r"(b[1]));
}
__device__ __forceinline__ uint32_t pack_hi2(float a, float b){
  __nv_bfloat162 t = __floats2bfloat162_rn(a, b);
  return *reinterpret_cast<uint32_t*>(&t);
}
__device__ __forceinline__ uint32_t pack_lo2(float a, float b){
  float ah = __bfloat162float(__float2bfloat16(a));
  float bh = __bfloat162float(__float2bfloat16(b));
  __nv_bfloat162 t = __floats2bfloat162_rn(a - ah, b - bh);
  return *reinterpret_cast<uint32_t*>(&t);
}

// ---------------- kernel 0: split + transpose weights ----------------
__global__ void prep_w_kernel(const float* __restrict__ Wq,
                              const float* __restrict__ Wk,
                              const float* __restrict__ Wv){
  int idx = blockIdx.x*blockDim.x + threadIdx.x;
  if (idx >= 192*512) return;
  int n192 = idx >> 9, k = idx & 511;
  int mat = n192 >> 6, n = n192 & 63;
  const float* W = (mat == 0) ? Wq : (mat == 1 ? Wk : Wv);
  float v = W[k*NH + n];
  __nv_bfloat16 h = __float2bfloat16(v);
  g_wth[idx] = h;
  g_wtl[idx] = __float2bfloat16(v - __bfloat162float(h));
}

// ---------------- kernel 1: fused QKV projection (split-bf16 MMA) ----------------
// CTA: 128 rows x 192 cols (Q|K|V), K-chunks of 64. 8 warps = 4(m) x 2(n), warp tile 32x96.
#define K1_XS 9216            // 128*72 halves
#define K1_WS 13824           // 192*72 halves
#define K1_SMEM ((2*K1_XS + 2*K1_WS)*2)

__global__ __launch_bounds__(256, 1) void qkv_kernel(const float* __restrict__ x){
  extern __shared__ __nv_bfloat16 sm1[];
  __nv_bfloat16* xh = sm1;
  __nv_bfloat16* xl = sm1 + K1_XS;
  __nv_bfloat16* wh = sm1 + 2*K1_XS;
  __nv_bfloat16* wl = wh  + K1_WS;

  const int t = threadIdx.x;
  const int w = t >> 5, lane = t & 31, g = lane >> 2, t4 = lane & 3;
  const int mw = w & 3, nw = w >> 2;
  const int row0 = blockIdx.x * 128;

  float acc[2][12][4];
  #pragma unroll
  for (int mt = 0; mt < 2; mt++)
    #pragma unroll
    for (int nt = 0; nt < 12; nt++)
      #pragma unroll
      for (int e = 0; e < 4; e++) acc[mt][nt][e] = 0.f;

  float4 xr[8];
  // prologue: prefetch x chunk 0 into registers
  #pragma unroll
  for (int i = 0; i < 8; i++){
    int idx4 = i*256 + t;
    int r = idx4 >> 4, c4 = (idx4 & 15) << 2;
    xr[i] = *reinterpret_cast<const float4*>(x + (size_t)(row0 + r)*NC + 0*64 + c4);
  }

  for (int kc = 0; kc < 8; kc++){
    // ---- stage x tile from registers (hi/lo bf16, padded stride 72) ----
    #pragma unroll
    for (int i = 0; i < 8; i++){
      int idx4 = i*256 + t;
      int r = idx4 >> 4, c4 = (idx4 & 15) << 2;
      float4 v = xr[i];
      __nv_bfloat162 h01, h23, l01, l23;
      h01.x = __float2bfloat16(v.x); l01.x = __float2bfloat16(v.x - __bfloat162float(h01.x));
      h01.y = __float2bfloat16(v.y); l01.y = __float2bfloat16(v.y - __bfloat162float(h01.y));
      h23.x = __float2bfloat16(v.z); l23.x = __float2bfloat16(v.z - __bfloat162float(h23.x));
      h23.y = __float2bfloat16(v.w); l23.y = __float2bfloat16(v.w - __bfloat162float(h23.y));
      *reinterpret_cast<__nv_bfloat162*>(&xh[r*72 + c4    ]) = h01;
      *reinterpret_cast<__nv_bfloat162*>(&xh[r*72 + c4 + 2]) = h23;
      *reinterpret_cast<__nv_bfloat162*>(&xl[r*72 + c4    ]) = l01;
      *reinterpret_cast<__nv_bfloat162*>(&xl[r*72 + c4 + 2]) = l23;
    }
    // ---- stage W tiles (direct LDG->STS; W is L2-resident after first wave) ----
    #pragma unroll
    for (int i = 0; i < 12; i++){
      int idx4 = i*256 + t;
      int n192 = idx4 >> 4, c4 = (idx4 & 15) << 2;
      *reinterpret_cast<uint2*>(&wh[n192*72 + c4]) =
          *reinterpret_cast<const uint2*>(&g_wth[n192*512 + kc*64 + c4]);
      *reinterpret_cast<uint2*>(&wl[n192*72 + c4]) =
          *reinterpret_cast<const uint2*>(&g_wtl[n192*512 + kc*64 + c4]);
    }
    __syncthreads();

    // ---- prefetch next x chunk into registers (overlaps MMA below) ----
    if (kc < 7){
      #pragma unroll
      for (int i = 0; i < 8; i++){
        int idx4 = i*256 + t;
        int r = idx4 >> 4, c4 = (idx4 & 15) << 2;
        xr[i] = *reinterpret_cast<const float4*>(x + (size_t)(row0 + r)*NC + (kc+1)*64 + c4);
      }
    }

    // ---- MMA, term-pass ordered ----
    #pragma unroll
    for (int ks = 0; ks < 4; ks++){
      int ko = ks*16;
      uint32_t ah[2][4], al[2][4];
      #pragma unroll
      for (int mt = 0; mt < 2; mt++){
        int rb = mw*32 + mt*16;
        ah[mt][0] = *reinterpret_cast<const uint32_t*>(&xh[(rb+g  )*72 + ko + 2*t4    ]);
        ah[mt][1] = *reinterpret_cast<const uint32_t*>(&xh[(rb+g+8)*72 + ko + 2*t4    ]);
        ah[mt][2] = *reinterpret_cast<const uint32_t*>(&xh[(rb+g  )*72 + ko + 2*t4 + 8]);
        ah[mt][3] = *reinterpret_cast<const uint32_t*>(&xh[(rb+g+8)*72 + ko + 2*t4 + 8]);
        al[mt][0] = *reinterpret_cast<const uint32_t*>(&xl[(rb+g  )*72 + ko + 2*t4    ]);
        al[mt][1] = *reinterpret_cast<const uint32_t*>(&xl[(rb+g+8)*72 + ko + 2*t4    ]);
        al[mt][2] = *reinterpret_cast<const uint32_t*>(&xl[(rb+g  )*72 + ko + 2*t4 + 8]);
        al[mt][3] = *reinterpret_cast<const uint32_t*>(&xl[(rb+g+8)*72 + ko + 2*t4 + 8]);
      }
      uint32_t bb[12][2];
      #pragma unroll
      for (int nt = 0; nt < 12; nt++){
        int nb = nw*96 + nt*8;
        bb[nt][0] = *reinterpret_cast<const uint32_t*>(&wh[(nb+g)*72 + ko + 2*t4    ]);
        bb[nt][1] = *reinterpret_cast<const uint32_t*>(&wh[(nb+g)*72 + ko + 2*t4 + 8]);
      }
      #pragma unroll
      for (int nt = 0; nt < 12; nt++){          // pass 1: xh * wh
        mma16816(acc[0][nt], ah[0], bb[nt]);
        mma16816(acc[1][nt], ah[1], bb[nt]);
      }
      #pragma unroll
      for (int nt = 0; nt < 12; nt++){          // pass 2: xl * wh
        mma16816(acc[0][nt], al[0], bb[nt]);
        mma16816(acc[1][nt], al[1], bb[nt]);
      }
      #pragma unroll
      for (int nt = 0; nt < 12; nt++){
        int nb = nw*96 + nt*8;
        bb[nt][0] = *reinterpret_cast<const uint32_t*>(&wl[(nb+g)*72 + ko + 2*t4    ]);
        bb[nt][1] = *reinterpret_cast<const uint32_t*>(&wl[(nb+g)*72 + ko + 2*t4 + 8]);
      }
      #pragma unroll
      for (int nt = 0; nt < 12; nt++){          // pass 3: xh * wl
        mma16816(acc[0][nt], ah[0], bb[nt]);
        mma16816(acc[1][nt], ah[1], bb[nt]);
      }
    }
    __syncthreads();
  }

  // epilogue: split fp32 accum -> hi/lo bf16 scratch
  #pragma unroll
  for (int mt = 0; mt < 2; mt++){
    #pragma unroll
    for (int nt = 0; nt < 12; nt++){
      int col = nw*96 + nt*8 + 2*t4;
      int mat = col >> 6, h = col & 63;
      __nv_bfloat16* dh = (mat == 0) ? g_qh : (mat == 1 ? g_kh : g_vh);
      __nv_bfloat16* dl = (mat == 0) ? g_ql : (mat == 1 ? g_kl : g_vl);
      int r0g = row0 + mw*32 + mt*16 + g;
      float c0 = acc[mt][nt][0], c1 = acc[mt][nt][1];
      float c2 = acc[mt][nt][2], c3 = acc[mt][nt][3];
      __nv_bfloat162 hh, ll;
      hh.x = __float2bfloat16(c0); ll.x = __float2bfloat16(c0 - __bfloat162float(hh.x));
      hh.y = __float2bfloat16(c1); ll.y = __float2bfloat16(c1 - __bfloat162float(hh.y));
      *reinterpret_cast<__nv_bfloat162*>(&dh[(size_t)r0g*NH + h]) = hh;
      *reinterpret_cast<__nv_bfloat162*>(&dl[(size_t)r0g*NH + h]) = ll;
      hh.x = __float2bfloat16(c2); ll.x = __float2bfloat16(c2 - __bfloat162float(hh.x));
      hh.y = __float2bfloat16(c3); ll.y = __float2bfloat16(c3 - __bfloat162float(hh.y));
      *reinterpret_cast<__nv_bfloat162*>(&dh[(size_t)(r0g+8)*NH + h]) = hh;
      *reinterpret_cast<__nv_bfloat162*>(&dl[(size_t)(r0g+8)*NH + h]) = ll;
    }
  }
}

// ---------------- kernel 2: causal attention (flash-style, split-bf16 MMA) ----------------
#define A_QH 0
#define A_QL 9216
#define A_KH 18432
#define A_KL 36864
#define A_VH 55296
#define A_VL 72320
#define A_TOT 89344
#define K2_SMEM (A_TOT*2)
#define VSTR 266

__global__ __launch_bounds__(256, 1) void attn_kernel(float* __restrict__ out){
  extern __shared__ __nv_bfloat16 sm2[];
  __nv_bfloat16* qh  = sm2 + A_QH;
  __nv_bfloat16* ql  = sm2 + A_QL;
  __nv_bfloat16* kh  = sm2 + A_KH;
  __nv_bfloat16* kl  = sm2 + A_KL;
  __nv_bfloat16* vth = sm2 + A_VH;
  __nv_bfloat16* vtl = sm2 + A_VL;

  const int b   = blockIdx.x >> 1;
  const int blk = blockIdx.x & 1;
  const int t = threadIdx.x, w = t >> 5, lane = t & 31, g = lane >> 2, t4 = lane & 3;
  const int nk = (blk + 1) * 128;
  const size_t base = (size_t)b * (NT*NH);

  #pragma unroll
  for (int i = 0; i < 8; i++){
    int idx4 = i*256 + t;
    int r = idx4 >> 4, c4 = (idx4 & 15) << 2;
    *reinterpret_cast<uint2*>(&qh[r*72 + c4]) =
        *reinterpret_cast<const uint2*>(&g_qh[base + (size_t)(blk*128 + r)*NH + c4]);
    *reinterpret_cast<uint2*>(&ql[r*72 + c4]) =
        *reinterpret_cast<const uint2*>(&g_ql[base + (size_t)(blk*128 + r)*NH + c4]);
  }
  for (int idx4 = t; idx4 < nk*16; idx4 += 256){
    int r = idx4 >> 4, c4 = (idx4 & 15) << 2;
    *reinterpret_cast<uint2*>(&kh[r*72 + c4]) =
        *reinterpret_cast<const uint2*>(&g_kh[base + (size_t)r*NH + c4]);
    *reinterpret_cast<uint2*>(&kl[r*72 + c4]) =
        *reinterpret_cast<const uint2*>(&g_kl[base + (size_t)r*NH + c4]);
  }
  for (int idx4 = t; idx4 < nk*16; idx4 += 256){
    int s = idx4 >> 4, h4 = (idx4 & 15) << 2;
    uint2 vh2 = *reinterpret_cast<const uint2*>(&g_vh[base + (size_t)s*NH + h4]);
    uint2 vl2 = *reinterpret_cast<const uint2*>(&g_vl[base + (size_t)s*NH + h4]);
    const __nv_bfloat162* ph = reinterpret_cast<const __nv_bfloat162*>(&vh2);
    const __nv_bfloat162* pl = reinterpret_cast<const __nv_bfloat162*>(&vl2);
    vth[(h4+0)*VSTR + s] = ph[0].x;  vth[(h4+1)*VSTR + s] = ph[0].y;
    vth[(h4+2)*VSTR + s] = ph[1].x;  vth[(h4+3)*VSTR + s] = ph[1].y;
    vtl[(h4+0)*VSTR + s] = pl[0].x;  vtl[(h4+1)*VSTR + s] = pl[0].y;
    vtl[(h4+2)*VSTR + s] = pl[1].x;  vtl[(h4+3)*VSTR + s] = pl[1].y;
  }
  __syncthreads();

  const int rb  = blk*128 + w*16;
  const int lrb = w*16;

  // ---- hoist Q fragments (loop-invariant over j), scalar loads ----
  uint32_t qa[4][4], qla[4][4];
  #pragma unroll
  for (int ks = 0; ks < 4; ks++){
    int ko = ks*16;
    qa[ks][0]  = *reinterpret_cast<const uint32_t*>(&qh[(lrb+g  )*72 + ko + 2*t4    ]);
    qa[ks][1]  = *reinterpret_cast<const uint32_t*>(&qh[(lrb+g+8)*72 + ko + 2*t4    ]);
    qa[ks][2]  = *reinterpret_cast<const uint32_t*>(&qh[(lrb+g  )*72 + ko + 2*t4 + 8]);
    qa[ks][3]  = *reinterpret_cast<const uint32_t*>(&qh[(lrb+g+8)*72 + ko + 2*t4 + 8]);
    qla[ks][0] = *reinterpret_cast<const uint32_t*>(&ql[(lrb+g  )*72 + ko + 2*t4    ]);
    qla[ks][1] = *reinterpret_cast<const uint32_t*>(&ql[(lrb+g+8)*72 + ko + 2*t4    ]);
    qla[ks][2] = *reinterpret_cast<const uint32_t*>(&ql[(lrb+g  )*72 + ko + 2*t4 + 8]);
    qla[ks][3] = *reinterpret_cast<const uint32_t*>(&ql[(lrb+g+8)*72 + ko + 2*t4 + 8]);
  }

  float m_[2] = {-1e30f, -1e30f};
  float l_[2] = {0.f, 0.f};
  float o[8][4];
  #pragma unroll
  for (int nt = 0; nt < 8; nt++)
    #pragma unroll
    for (int e = 0; e < 4; e++) o[nt][e] = 0.f;

  const int jmax = (rb + 15) >> 6;
  for (int j = 0; j <= jmax; j++){
    float s[8][4];
    #pragma unroll
    for (int nt = 0; nt < 8; nt++)
      #pragma unroll
      for (int e = 0; e < 4; e++) s[nt][e] = 0.f;

    // ---- S = Q K^T, term-pass ordered ----
    #pragma unroll
    for (int ks = 0; ks < 4; ks++){
      int ko = ks*16;
      uint32_t kb[8][2];
      #pragma unroll
      for (int nt = 0; nt < 8; nt++){
        int kr = j*64 + nt*8 + g;
        kb[nt][0] = *reinterpret_cast<const uint32_t*>(&kh[kr*72 + ko + 2*t4    ]);
        kb[nt][1] = *reinterpret_cast<const uint32_t*>(&kh[kr*72 + ko + 2*t4 + 8]);
      }
      #pragma unroll
      for (int nt = 0; nt < 8; nt++) mma16816(s[nt], qa[ks],  kb[nt]);   // qh*kh
      #pragma unroll
      for (int nt = 0; nt < 8; nt++) mma16816(s[nt], qla[ks], kb[nt]);   // ql*kh
      #pragma unroll
      for (int nt = 0; nt < 8; nt++){
        int kr = j*64 + nt*8 + g;
        kb[nt][0] = *reinterpret_cast<const uint32_t*>(&kl[kr*72 + ko + 2*t4    ]);
        kb[nt][1] = *reinterpret_cast<const uint32_t*>(&kl[kr*72 + ko + 2*t4 + 8]);
      }
      #pragma unroll
      for (int nt = 0; nt < 8; nt++) mma16816(s[nt], qa[ks],  kb[nt]);   // qh*kl
    }

    // ---- scale + causal mask ----
    const bool needm = (j*64 + 63 > rb);
    #pragma unroll
    for (int nt = 0; nt < 8; nt++){
      #pragma unroll
      for (int e = 0; e < 4; e++){
        float v = s[nt][e] * 0.125f;
        if (needm){
          int col = j*64 + nt*8 + 2*t4 + (e & 1);
          int row = rb + g + ((e & 2) ? 8 : 0);
          if (col > row) v = -1e30f;
        }
        s[nt][e] = v;
      }
    }

    // ---- online softmax ----
    float mx0 = -1e30f, mx1 = -1e30f;
    #pragma unroll
    for (int nt = 0; nt < 8; nt++){
      mx0 = fmaxf(mx0, fmaxf(s[nt][0], s[nt][1]));
      mx1 = fmaxf(mx1, fmaxf(s[nt][2], s[nt][3]));
    }
    mx0 = fmaxf(mx0, __shfl_xor_sync(0xffffffffu, mx0, 1));
    mx0 = fmaxf(mx0, __shfl_xor_sync(0xffffffffu, mx0, 2));
    mx1 = fmaxf(mx1, __shfl_xor_sync(0xffffffffu, mx1, 1));
    mx1 = fmaxf(mx1, __shfl_xor_sync(0xffffffffu, mx1, 2));
    float mn0 = fmaxf(m_[0], mx0), mn1 = fmaxf(m_[1], mx1);
    float cr0 = __expf(m_[0] - mn0), cr1 = __expf(m_[1] - mn1);
    m_[0] = mn0; m_[1] = mn1;

    float rs0 = 0.f, rs1 = 0.f;
    #pragma unroll
    for (int nt = 0; nt < 8; nt++){
      s[nt][0] = __expf(s[nt][0] - mn0); rs0 += s[nt][0];
      s[nt][1] = __expf(s[nt][1] - mn0); rs0 += s[nt][1];
      s[nt][2] = __expf(s[nt][2] - mn1); rs1 += s[nt][2];
      s[nt][3] = __expf(s[nt][3] - mn1); rs1 += s[nt][3];
    }
    rs0 += __shfl_xor_sync(0xffffffffu, rs0, 1);
    rs0 += __shfl_xor_sync(0xffffffffu, rs0, 2);
    rs1 += __shfl_xor_sync(0xffffffffu, rs1, 1);
    rs1 += __shfl_xor_sync(0xffffffffu, rs1, 2);
    l_[0] = l_[0]*cr0 + rs0;
    l_[1] = l_[1]*cr1 + rs1;
    #pragma unroll
    for (int nt = 0; nt < 8; nt++){
      o[nt][0] *= cr0; o[nt][1] *= cr0;
      o[nt][2] *= cr1; o[nt][3] *= cr1;
    }

    // ---- O += P V, term-pass ordered ----
    #pragma unroll
    for (int ks2 = 0; ks2 < 4; ks2++){
      uint32_t ph[4], pl[4];
      ph[0] = pack_hi2(s[2*ks2  ][0], s[2*ks2  ][1]);
      ph[1] = pack_hi2(s[2*ks2  ][2], s[2*ks2  ][3]);
      ph[2] = pack_hi2(s[2*ks2+1][0], s[2*ks2+1][1]);
      ph[3] = pack_hi2(s[2*ks2+1][2], s[2*ks2+1][3]);
      pl[0] = pack_lo2(s[2*ks2  ][0], s[2*ks2  ][1]);
      pl[1] = pack_lo2(s[2*ks2  ][2], s[2*ks2  ][3]);
      pl[2] = pack_lo2(s[2*ks2+1][0], s[2*ks2+1][1]);
      pl[3] = pack_lo2(s[2*ks2+1][2], s[2*ks2+1][3]);
      int sb2 = j*64 + ks2*16;
      uint32_t vb[8][2];
      #pragma unroll
      for (int nt2 = 0; nt2 < 8; nt2++){
        vb[nt2][0] = *reinterpret_cast<const uint32_t*>(&vth[(nt2*8+g)*VSTR + sb2 + 2*t4    ]);
        vb[nt2][1] = *reinterpret_cast<const uint32_t*>(&vth[(nt2*8+g)*VSTR + sb2 + 2*t4 + 8]);
      }
      #pragma unroll
      for (int nt2 = 0; nt2 < 8; nt2++) mma16816(o[nt2], ph, vb[nt2]);   // ph*vh
      #pragma unroll
      for (int nt2 = 0; nt2 < 8; nt2++) mma16816(o[nt2], pl, vb[nt2]);   // pl*vh
      #pragma unroll
      for (int nt2 = 0; nt2 < 8; nt2++){
        vb[nt2][0] = *reinterpret_cast<const uint32_t*>(&vtl[(nt2*8+g)*VSTR + sb2 + 2*t4    ]);
        vb[nt2][1] = *reinterpret_cast<const uint32_t*>(&vtl[(nt2*8+g)*VSTR + sb2 + 2*t4 + 8]);
      }
      #pragma unroll
      for (int nt2 = 0; nt2 < 8; nt2++) mma16816(o[nt2], ph, vb[nt2]);   // ph*vl
    }
  }

  float inv0 = 1.f / l_[0], inv1 = 1.f / l_[1];
  #pragma unroll
  for (int nt2 = 0; nt2 < 8; nt2++){
    int col = nt2*8 + 2*t4;
    size_t o0 = base + (size_t)(rb + g)*NH + col;
    float2 v01 = make_float2(o[nt2][0]*inv0, o[nt2][1]*inv0);
    float2 v23 = make_float2(o[nt2][2]*inv1, o[nt2][3]*inv1);
    *reinterpret_cast<float2*>(&out[o0])        = v01;
    *reinterpret_cast<float2*>(&out[o0 + 8*NH]) = v23;
  }
}

// ---------------- launch ----------------
extern "C" void kernel_launch(void* const* d_in, const int* in_sizes, int n_in,
                              void* d_out, int out_size){
  const float* x  = (const float*)d_in[0];
  const float* Wq = (const float*)d_in[1];
  const float* Wk = (const float*)d_in[2];
  const float* Wv = (const float*)d_in[3];
  float* out = (float*)d_out;

  cudaFuncSetAttribute(qkv_kernel,  cudaFuncAttributeMaxDynamicSharedMemorySize, K1_SMEM);
  cudaFuncSetAttribute(attn_kernel, cudaFuncAttributeMaxDynamicSharedMemorySize, K2_SMEM);

  prep_w_kernel<<<384, 256>>>(Wq, Wk, Wv);
  qkv_kernel<<<2048, 256, K1_SMEM>>>(x);
  attn_kernel<<<2048, 256, K2_SMEM>>>(out);
}